// round 4
// baseline (speedup 1.0000x reference)
#include <cuda_runtime.h>

// predict/target: [2, 4, 64, 256, 256] fp32 -> 512 slices of 65536 elems.
#define HW              65536
#define NSLICES         512
#define SLICE_D         64
#define NPAIRS          8
#define TPB             128
#define CTAS_PER_SLICE  2
#define GRID            (NSLICES * CTAS_PER_SLICE)   // 1024
#define CHUNK_F4        (HW / 4 / CTAS_PER_SLICE)    // 8192 float4 per CTA
#define ITERS           (CHUNK_F4 / TPB)             // 64 per thread
#define BATCH           4
#define OUTER           (ITERS / BATCH)              // 16

__device__ float        g_num[NSLICES];
__device__ float        g_sp [NSLICES];
__device__ float        g_st [NSLICES];
__device__ unsigned int g_done;

// sigmoid(x) = 0.5 * tanh(0.5 x) + 0.5  (tanh.approx.f32: 1 MUFU op)
__device__ __forceinline__ float fast_sigmoid(float x) {
    float t;
    asm("tanh.approx.f32 %0, %1;" : "=f"(t) : "f"(x * 0.5f));
    return fmaf(0.5f, t, 0.5f);
}

__device__ __forceinline__ void accum4(const float4& a, const float4& b,
                                       float& num, float& sp, float& st) {
    float s0 = fast_sigmoid(a.x);
    float s1 = fast_sigmoid(a.y);
    float s2 = fast_sigmoid(a.z);
    float s3 = fast_sigmoid(a.w);
    num += s0 * b.x + s1 * b.y + s2 * b.z + s3 * b.w;
    sp  += s0 + s1 + s2 + s3;
    st  += b.x + b.y + b.z + b.w;
}

__global__ __launch_bounds__(TPB, 8)
void dice_fused_kernel(const float* __restrict__ predict,
                       const float* __restrict__ target,
                       float* __restrict__ out) {
    const int cta  = blockIdx.x;
    const int s    = cta >> 1;
    const int half = cta & 1;
    const int tid  = threadIdx.x;

    const size_t base = (size_t)s * (HW / 4) + (size_t)half * CHUNK_F4 + tid;
    const float4* __restrict__ p = reinterpret_cast<const float4*>(predict) + base;
    const float4* __restrict__ t = reinterpret_cast<const float4*>(target)  + base;

    float num = 0.0f, sp = 0.0f, st = 0.0f;

    #pragma unroll 1
    for (int it = 0; it < OUTER; ++it) {
        // Front-batched loads: 8 LDG.128 issued back-to-back (high MLP).
        float4 a0 = p[0 * TPB];
        float4 a1 = p[1 * TPB];
        float4 a2 = p[2 * TPB];
        float4 a3 = p[3 * TPB];
        float4 b0 = t[0 * TPB];
        float4 b1 = t[1 * TPB];
        float4 b2 = t[2 * TPB];
        float4 b3 = t[3 * TPB];
        p += BATCH * TPB;
        t += BATCH * TPB;

        accum4(a0, b0, num, sp, st);
        accum4(a1, b1, num, sp, st);
        accum4(a2, b2, num, sp, st);
        accum4(a3, b3, num, sp, st);
    }

    // Warp reduce the three accumulators.
    #pragma unroll
    for (int off = 16; off > 0; off >>= 1) {
        num += __shfl_down_sync(0xffffffffu, num, off);
        sp  += __shfl_down_sync(0xffffffffu, sp,  off);
        st  += __shfl_down_sync(0xffffffffu, st,  off);
    }

    __shared__ float s_num[TPB / 32];
    __shared__ float s_sp [TPB / 32];
    __shared__ float s_st [TPB / 32];
    __shared__ bool  s_last;

    const int lane = tid & 31;
    const int wid  = tid >> 5;
    if (lane == 0) { s_num[wid] = num; s_sp[wid] = sp; s_st[wid] = st; }
    __syncthreads();

    if (tid == 0) {
        float n = 0.0f, a = 0.0f, b = 0.0f;
        #pragma unroll
        for (int w = 0; w < TPB / 32; w++) { n += s_num[w]; a += s_sp[w]; b += s_st[w]; }
        atomicAdd(&g_num[s], n);
        atomicAdd(&g_sp [s], a);
        atomicAdd(&g_st [s], b);
        __threadfence();
        unsigned int d = atomicAdd(&g_done, 1u);
        s_last = (d == GRID - 1);
    }
    __syncthreads();

    // ---- Fused finalize: last CTA reduces all 512 slices ----
    if (s_last) {
        __threadfence();  // acquire: all producer atomics visible

        __shared__ float p_sum[NPAIRS];
        __shared__ float p_cnt[NPAIRS];
        if (tid < NPAIRS) { p_sum[tid] = 0.0f; p_cnt[tid] = 0.0f; }
        __syncthreads();

        for (int i = tid; i < NSLICES; i += TPB) {
            float n = g_num[i];
            float a = g_sp [i];
            float b = g_st [i];
            float dice = 1.0f - 2.0f * n / (a + b + 1.0f);
            float v = (target[(size_t)i * HW] != -1.0f) ? 1.0f : 0.0f;
            atomicAdd(&p_sum[i / SLICE_D], dice * v);
            atomicAdd(&p_cnt[i / SLICE_D], v);
            // Reset state for the next graph replay.
            g_num[i] = 0.0f; g_sp[i] = 0.0f; g_st[i] = 0.0f;
        }
        __syncthreads();

        if (tid == 0) {
            float acc = 0.0f;
            #pragma unroll
            for (int i = 0; i < NPAIRS; i++) acc += p_sum[i] / p_cnt[i];
            out[0] = acc * (1.0f / (float)NPAIRS);
            g_done = 0u;
        }
    }
}

extern "C" void kernel_launch(void* const* d_in, const int* in_sizes, int n_in,
                              void* d_out, int out_size) {
    const float* predict = (const float*)d_in[0];
    const float* target  = (const float*)d_in[1];
    float* out = (float*)d_out;

    dice_fused_kernel<<<GRID, TPB>>>(predict, target, out);
}

// round 5
// speedup vs baseline: 1.1636x; 1.1636x over previous
#include <cuda_runtime.h>

// predict/target: [2, 4, 64, 256, 256] fp32 -> 512 slices of 65536 elems.
#define HW              65536
#define NSLICES         512
#define SLICE_D         64
#define NPAIRS          8
#define TPB             256
#define CTAS_PER_SLICE  8
#define GRID            (NSLICES * CTAS_PER_SLICE)       // 4096
#define CHUNK_F4        (HW / 4 / CTAS_PER_SLICE)        // 2048 float4 per CTA
#define ITERS           (CHUNK_F4 / TPB)                 // 8 per thread
#define BATCH           4
#define OUTER           (ITERS / BATCH)                  // 2

__device__ float        g_num[NSLICES];
__device__ float        g_sp [NSLICES];
__device__ float        g_st [NSLICES];
__device__ unsigned int g_done;

// sigmoid(x) = 0.5 * tanh(0.5 x) + 0.5  (tanh.approx.f32: 1 MUFU op)
__device__ __forceinline__ float fast_sigmoid(float x) {
    float t;
    asm("tanh.approx.f32 %0, %1;" : "=f"(t) : "f"(x * 0.5f));
    return fmaf(0.5f, t, 0.5f);
}

__device__ __forceinline__ void accum4(const float4& a, const float4& b,
                                       float& num, float& sp, float& st) {
    float s0 = fast_sigmoid(a.x);
    float s1 = fast_sigmoid(a.y);
    float s2 = fast_sigmoid(a.z);
    float s3 = fast_sigmoid(a.w);
    num += s0 * b.x + s1 * b.y + s2 * b.z + s3 * b.w;
    sp  += s0 + s1 + s2 + s3;
    st  += b.x + b.y + b.z + b.w;
}

__global__ __launch_bounds__(TPB)
void dice_fused_kernel(const float* __restrict__ predict,
                       const float* __restrict__ target,
                       float* __restrict__ out) {
    const int cta  = blockIdx.x;
    const int s    = cta / CTAS_PER_SLICE;
    const int part = cta % CTAS_PER_SLICE;
    const int tid  = threadIdx.x;

    const size_t base = (size_t)s * (HW / 4) + (size_t)part * CHUNK_F4 + tid;
    const float4* __restrict__ p = reinterpret_cast<const float4*>(predict) + base;
    const float4* __restrict__ t = reinterpret_cast<const float4*>(target)  + base;

    float num = 0.0f, sp = 0.0f, st = 0.0f;

    #pragma unroll
    for (int it = 0; it < OUTER; ++it) {
        // Front-batched loads: 8 LDG.128 issued back-to-back.
        float4 a0 = p[0 * TPB];
        float4 a1 = p[1 * TPB];
        float4 a2 = p[2 * TPB];
        float4 a3 = p[3 * TPB];
        float4 b0 = t[0 * TPB];
        float4 b1 = t[1 * TPB];
        float4 b2 = t[2 * TPB];
        float4 b3 = t[3 * TPB];
        p += BATCH * TPB;
        t += BATCH * TPB;

        accum4(a0, b0, num, sp, st);
        accum4(a1, b1, num, sp, st);
        accum4(a2, b2, num, sp, st);
        accum4(a3, b3, num, sp, st);
    }

    // Warp reduce the three accumulators.
    #pragma unroll
    for (int off = 16; off > 0; off >>= 1) {
        num += __shfl_down_sync(0xffffffffu, num, off);
        sp  += __shfl_down_sync(0xffffffffu, sp,  off);
        st  += __shfl_down_sync(0xffffffffu, st,  off);
    }

    __shared__ float s_num[TPB / 32];
    __shared__ float s_sp [TPB / 32];
    __shared__ float s_st [TPB / 32];
    __shared__ bool  s_last;

    const int lane = tid & 31;
    const int wid  = tid >> 5;
    if (lane == 0) { s_num[wid] = num; s_sp[wid] = sp; s_st[wid] = st; }
    __syncthreads();

    if (tid == 0) {
        float n = 0.0f, a = 0.0f, b = 0.0f;
        #pragma unroll
        for (int w = 0; w < TPB / 32; w++) { n += s_num[w]; a += s_sp[w]; b += s_st[w]; }
        atomicAdd(&g_num[s], n);
        atomicAdd(&g_sp [s], a);
        atomicAdd(&g_st [s], b);
        __threadfence();
        unsigned int d = atomicAdd(&g_done, 1u);
        s_last = (d == GRID - 1);
    }
    __syncthreads();

    // ---- Fused finalize: last CTA reduces all 512 slices ----
    if (s_last) {
        __threadfence();  // acquire: all producer atomics visible

        __shared__ float p_sum[NPAIRS];
        __shared__ float p_cnt[NPAIRS];
        if (tid < NPAIRS) { p_sum[tid] = 0.0f; p_cnt[tid] = 0.0f; }
        __syncthreads();

        for (int i = tid; i < NSLICES; i += TPB) {
            float n = g_num[i];
            float a = g_sp [i];
            float b = g_st [i];
            float dice = 1.0f - 2.0f * n / (a + b + 1.0f);
            float v = (target[(size_t)i * HW] != -1.0f) ? 1.0f : 0.0f;
            atomicAdd(&p_sum[i / SLICE_D], dice * v);
            atomicAdd(&p_cnt[i / SLICE_D], v);
            // Reset state for the next graph replay.
            g_num[i] = 0.0f; g_sp[i] = 0.0f; g_st[i] = 0.0f;
        }
        __syncthreads();

        if (tid == 0) {
            float acc = 0.0f;
            #pragma unroll
            for (int i = 0; i < NPAIRS; i++) acc += p_sum[i] / p_cnt[i];
            out[0] = acc * (1.0f / (float)NPAIRS);
            g_done = 0u;
        }
    }
}

extern "C" void kernel_launch(void* const* d_in, const int* in_sizes, int n_in,
                              void* d_out, int out_size) {
    const float* predict = (const float*)d_in[0];
    const float* target  = (const float*)d_in[1];
    float* out = (float*)d_out;

    dice_fused_kernel<<<GRID, TPB>>>(predict, target, out);
}